// round 5
// baseline (speedup 1.0000x reference)
#include <cuda_runtime.h>
#include <cstdint>

#define NIMG 512
#define HW   1024

// ----------------------------------------------------------------------------
// scratch (device globals; no runtime allocation)
// ----------------------------------------------------------------------------
__device__ float    g_resin[(size_t)NIMG * HW * 32];  // NHWC, 25 real ch + pad
__device__ float    g_h[(size_t)NIMG * HW * 64];      // NHWC64
__device__ float    g_tmp[(size_t)NIMG * HW * 64];    // NHWC64
__device__ float    g_cout[(size_t)NIMG * HW * 16];   // NHWC, 9 real ch + pad
__device__ float    g_alpha[NIMG];
__device__ float    g_araw[NIMG];
__device__ uint32_t g_wfrag[18432 + 4 * 36864 + 9216]; // pre-scattered B frags

#define WOFF_IN   0
#define WOFF_HID0 18432
#define WOFF_OUT  (18432 + 4 * 36864)

__device__ __forceinline__ void mma_tf32(float d[4], uint32_t a0, uint32_t a1,
                                         uint32_t a2, uint32_t a3,
                                         uint32_t b0, uint32_t b1) {
    asm volatile(
        "mma.sync.aligned.m16n8k8.row.col.f32.tf32.tf32.f32 "
        "{%0,%1,%2,%3}, {%4,%5,%6,%7}, {%8,%9}, {%0,%1,%2,%3};"
        : "+f"(d[0]), "+f"(d[1]), "+f"(d[2]), "+f"(d[3])
        : "r"(a0), "r"(a1), "r"(a2), "r"(a3), "r"(b0), "r"(b1));
}

__device__ __forceinline__ void cp_async16(uint32_t dst, const void* src, uint32_t srcsize) {
    asm volatile("cp.async.ca.shared.global [%0], [%1], 16, %2;"
                 :: "r"(dst), "l"(src), "r"(srcsize) : "memory");
}
__device__ __forceinline__ void cp_commit() {
    asm volatile("cp.async.commit_group;" ::: "memory");
}
__device__ __forceinline__ void cp_wait0() {
    asm volatile("cp.async.wait_group 0;" ::: "memory");
}
__device__ __forceinline__ uint32_t smem_u32(const void* p) {
    uint32_t a;
    asm("{ .reg .u64 t; cvta.to.shared.u64 t, %1; cvt.u32.u64 %0, t; }"
        : "=r"(a) : "l"(p));
    return a;
}
__device__ __forceinline__ uint32_t f2tf32(float f) {
    uint32_t r;
    asm("cvt.rna.tf32.f32 %0, %1;" : "=r"(r) : "f"(f));
    return r;
}

// ----------------------------------------------------------------------------
// weight prep: natural OIHW -> B-fragment layout (one-time, 6 blocks)
// k-permutation: within each 8-channel group, channel 2q -> k'=q, 2q+1 -> k'=q+4
// ----------------------------------------------------------------------------
__global__ __launch_bounds__(256)
void wprep_kernel(const float* __restrict__ w_in, const float* __restrict__ w1s,
                  const float* __restrict__ w2s, const float* __restrict__ w_out,
                  uint32_t* __restrict__ wfrag)
{
    const int layer = blockIdx.x;     // 0=in, 1..4=hidden, 5=out
    const int tid = threadIdx.x;

    const float* w;
    int cin, cout, nt8, woff, nwords;
    if (layer == 0)      { w = w_in;  cin = 25; cout = 64; nt8 = 8; woff = WOFF_IN;  nwords = 18432; }
    else if (layer <= 4) {
        const int blk = (layer - 1) >> 1;
        w = ((layer - 1) & 1) ? (w2s + (size_t)blk * 64 * 64 * 9)
                              : (w1s + (size_t)blk * 64 * 64 * 9);
        cin = 64; cout = 64; nt8 = 8; woff = WOFF_HID0 + (layer - 1) * 36864; nwords = 36864;
    }
    else                 { w = w_out; cin = 64; cout = 9;  nt8 = 2; woff = WOFF_OUT; nwords = 9216; }

    for (int i = tid; i < nwords; i += 256) wfrag[woff + i] = 0u;
    __syncthreads();

    const int wtot = cout * cin * 9;
    for (int i = tid; i < wtot; i += 256) {
        const int tap = i % 9;
        const int ci  = (i / 9) % cin;
        const int co  = i / (9 * cin);
        const int cg  = ci >> 5;
        const int kin = ci & 31;
        const int w8  = kin & 7;
        const int kkp = (kin & 24) | (w8 >> 1) | ((w8 & 1) << 2);
        const int kg  = (cg * 9 + tap) * 32 + kkp;
        const int chunk = kg >> 3;
        const int kk    = kg & 7;
        const int h     = kk >> 2;
        const int bl    = ((co & 7) << 2) | (kk & 3);
        const int nt    = co >> 3;
        wfrag[woff + (((chunk * nt8 + nt) * 32 + bl) << 1) + h] = f2tf32(w[i]);
    }
}

// ----------------------------------------------------------------------------
// prep: keyframe lerp -> NHWC32 res_in
// ----------------------------------------------------------------------------
__global__ __launch_bounds__(256)
void prep_kernel(const float* __restrict__ latents, const int* __restrict__ idx,
                 float* __restrict__ resin, float* __restrict__ alpha_arr,
                 float* __restrict__ araw_arr)
{
    const int n = blockIdx.x;
    const int b = n >> 7;
    const int t = n & 127;

    int v[9];
#pragma unroll
    for (int k = 0; k < 9; k++) v[k] = idx[b * 9 + k];
#pragma unroll
    for (int i = 1; i < 9; i++) {
        int key = v[i]; int j = i - 1;
        while (j >= 0 && v[j] > key) { v[j + 1] = v[j]; j--; }
        v[j + 1] = key;
    }
    int cnt = 0;
#pragma unroll
    for (int k = 0; k < 9; k++) cnt += (v[k] <= t);
    int seg = min(max(cnt - 1, 0), 7);
    const int t0 = v[seg], t1 = v[seg + 1];
    const float araw = (float)(t - t0) / (float)max(t1 - t0, 1);
    const float a = fminf(fmaxf(araw, 0.f), 1.f);

    const int tid = threadIdx.x;
    const float* L0 = latents + ((size_t)(b * 128 + t0)) * 8 * HW;
    const float* L1 = latents + ((size_t)(b * 128 + t1)) * 8 * HW;
    float* R = resin + (size_t)n * HW * 32;

#pragma unroll
    for (int j = 0; j < 4; j++) {
        const int p = tid + 256 * j;
        float buf[32];
#pragma unroll
        for (int c = 0; c < 8; c++) {
            const float z0 = L0[c * HW + p];
            const float z1 = L1[c * HW + p];
            buf[c]      = (1.f - a) * z0 + a * z1;
            buf[8 + c]  = z0;
            buf[16 + c] = z1;
        }
        buf[24] = a;
#pragma unroll
        for (int c = 25; c < 32; c++) buf[c] = 0.f;
        float4* dst = (float4*)(R + (size_t)p * 32);
#pragma unroll
        for (int q = 0; q < 8; q++)
            dst[q] = make_float4(buf[q*4], buf[q*4+1], buf[q*4+2], buf[q*4+3]);
    }
    if (tid == 0) { alpha_arr[n] = a; araw_arr[n] = araw; }
}

// ----------------------------------------------------------------------------
// implicit-GEMM 3x3 SAME conv, mma.sync m16n8k8 tf32, M32xN64 per warp.
// One CTA per image; 4 spatial tiles of 16x16 px; window 18x18 in SMEM,
// pixel stride CIN with XOR swizzle (c ^ ((pix&3)<<3)) for conflict-free LDS.64.
// ----------------------------------------------------------------------------
template<int CG, int NT8, bool SILU, bool RESID>
__global__ __launch_bounds__(256, 1)
void conv_mma(const float* __restrict__ in, const uint32_t* __restrict__ wfrag,
              const float* __restrict__ bias, float* __restrict__ out,
              const float* __restrict__ resid)
{
    constexpr int CIN  = CG * 32;
    constexpr int COUT = NT8 * 8;
    constexpr int BW   = CG * 36 * NT8 * 64;   // B words
    constexpr int CHK  = CIN / 4;              // 16B chunks per pixel

    extern __shared__ uint32_t smem[];
    uint32_t* b_s = smem;                      // BW words
    uint32_t* X_s = smem + BW;                 // 324*CIN words

    const int tid  = threadIdx.x;
    const int wid  = tid >> 5;
    const int lane = tid & 31;
    const int n    = blockIdx.x;
    const int tx   = lane >> 2;
    const int kq2  = (lane & 3) * 2;

    const uint32_t xs_u = smem_u32(X_s);
    const uint32_t bs_u = smem_u32(b_s);

    // ---- stage B fragments (once) ----
    for (int i = tid; i < BW / 4; i += 256)
        cp_async16(bs_u + i * 16, wfrag + i * 4, 16);

    // bias -> registers (guard OOB for the 9-channel output layer)
    float bv[NT8][2];
#pragma unroll
    for (int nt = 0; nt < NT8; nt++) {
        const int bi = nt * 8 + kq2;
        bv[nt][0] = (NT8 == 8 || bi     < 9) ? bias[bi]     : 0.f;
        bv[nt][1] = (NT8 == 8 || bi + 1 < 9) ? bias[bi + 1] : 0.f;
    }

    for (int mt = 0; mt < 4; mt++) {
        const int y0 = (mt >> 1) << 4;
        const int x0 = (mt & 1) << 4;

        if (mt) __syncthreads();             // previous tile fully consumed

        // ---- stage 18x18 window via cp.async ----
        for (int i = tid; i < 324 * CHK; i += 256) {
            const int q   = i % CHK;
            const int pix = i / CHK;
            const int rr  = pix / 18;
            const int cc  = pix - rr * 18;
            const int gy  = y0 - 1 + rr;
            const int gx  = x0 - 1 + cc;
            const bool ok = (gy >= 0) && (gy < 32) && (gx >= 0) && (gx < 32);
            const float* src = in + ((size_t)n * HW + (ok ? gy * 32 + gx : 0)) * CIN + q * 4;
            const uint32_t dw = (uint32_t)pix * CIN + (((uint32_t)q * 4) ^ (((uint32_t)pix & 3) << 3));
            cp_async16(xs_u + dw * 4, src, ok ? 16u : 0u);
        }
        cp_commit();
        cp_wait0();
        __syncthreads();

        float d0[NT8][4], d1[NT8][4];
#pragma unroll
        for (int nt = 0; nt < NT8; nt++)
#pragma unroll
            for (int q = 0; q < 4; q++) { d0[nt][q] = 0.f; d1[nt][q] = 0.f; }

        // ---- K loop: CG*9 taps, 4 k8-chunks each ----
#pragma unroll 1
        for (int t = 0; t < CG * 9; t++) {
            const int cg  = (CG == 2) ? (t >= 9) : 0;
            const int tap = t - 9 * cg;
            const int dy  = tap / 3, dx = tap - 3 * (tap / 3);

            const int pixA = (2 * wid + dy) * 18 + tx + dx;   // frag0 (row 2w)
            const int pixB = pixA + 18;                        // frag1 (row 2w+1)
            const uint32_t baseA = (uint32_t)pixA * CIN + cg * 32 + kq2
                                   + (((uint32_t)pixA & 3) << 3);
            const uint32_t baseB = (uint32_t)pixB * CIN + cg * 32 + kq2
                                   + (((uint32_t)pixB & 3) << 3);
            const uint32_t* bp0 = b_s + (size_t)(t * 4) * NT8 * 64 + lane * 2;

#pragma unroll
            for (int j = 0; j < 4; j++) {
                const uint32_t jx = (uint32_t)j << 3;
                const uint2 pa0 = *(const uint2*)(X_s + (baseA ^ jx));
                const uint2 pa1 = *(const uint2*)(X_s + ((baseA + 8 * CIN) ^ jx));
                const uint2 pb0 = *(const uint2*)(X_s + (baseB ^ jx));
                const uint2 pb1 = *(const uint2*)(X_s + ((baseB + 8 * CIN) ^ jx));
                const uint32_t* bp = bp0 + (size_t)j * NT8 * 64;
#pragma unroll
                for (int nt = 0; nt < NT8; nt++) {
                    const uint2 b = *(const uint2*)(bp + nt * 64);
                    mma_tf32(d0[nt], pa0.x, pa1.x, pa0.y, pa1.y, b.x, b.y);
                    mma_tf32(d1[nt], pb0.x, pb1.x, pb0.y, pb1.y, b.x, b.y);
                }
            }
        }

        // ---- epilogue: two tile rows per warp ----
#pragma unroll
        for (int f = 0; f < 2; f++) {
            float (*d)[4] = f ? d1 : d0;
            const int gy = y0 + 2 * wid + f;
            const size_t gp0 = (size_t)n * HW + gy * 32 + x0 + tx;
            const size_t gp1 = gp0 + 8;
#pragma unroll
            for (int nt = 0; nt < NT8; nt++) {
                const int c = nt * 8 + kq2;
                float v00 = d[nt][0] + bv[nt][0];
                float v01 = d[nt][1] + bv[nt][1];
                float v10 = d[nt][2] + bv[nt][0];
                float v11 = d[nt][3] + bv[nt][1];
                if (SILU) {
                    v00 = v00 / (1.f + __expf(-v00));
                    v01 = v01 / (1.f + __expf(-v01));
                    v10 = v10 / (1.f + __expf(-v10));
                    v11 = v11 / (1.f + __expf(-v11));
                }
                if (RESID) {
                    const float2 r0 = *(const float2*)(resid + gp0 * COUT + c);
                    const float2 r1 = *(const float2*)(resid + gp1 * COUT + c);
                    v00 += r0.x; v01 += r0.y; v10 += r1.x; v11 += r1.y;
                }
                *(float2*)(out + gp0 * COUT + c) = make_float2(v00, v01);
                *(float2*)(out + gp1 * COUT + c) = make_float2(v10, v11);
            }
        }
    }
}

// ----------------------------------------------------------------------------
// finalize: z_hat (NCHW) + conf
// ----------------------------------------------------------------------------
__global__ __launch_bounds__(256)
void finalize_kernel(const float* __restrict__ resin, const float* __restrict__ co,
                     const float* __restrict__ alpha_arr, const float* __restrict__ araw_arr,
                     float* __restrict__ outp)
{
    const int n = blockIdx.x;
    const int tid = threadIdx.x;
    const float a  = alpha_arr[n];
    const float ar = araw_arr[n];
    const float s  = a * (1.f - a);
    const bool interior = (ar > 0.f) && (ar < 1.f);

#pragma unroll
    for (int j = 0; j < 4; j++) {
        const int p = tid + 256 * j;
        const float* R = resin + ((size_t)n * HW + p) * 32;
        const float* O = co + ((size_t)n * HW + p) * 16;
        float zb[8], res[9];
#pragma unroll
        for (int c = 0; c < 8; c++) zb[c] = R[c];
#pragma unroll
        for (int c = 0; c < 9; c++) res[c] = O[c];
#pragma unroll
        for (int c = 0; c < 8; c++)
            outp[((size_t)n * 8 + c) * HW + p] = zb[c] + s * res[c];
        const float unc = 1.f / (1.f + __expf(-res[8]));
        outp[(size_t)NIMG * 8 * HW + (size_t)n * HW + p] =
            interior ? fminf(fmaxf(1.f - unc, 0.f), 1.f) : 1.f;
    }
}

// ----------------------------------------------------------------------------
// launch
// ----------------------------------------------------------------------------
extern "C" void kernel_launch(void* const* d_in, const int* in_sizes, int n_in,
                              void* d_out, int out_size)
{
    const float* latents = (const float*)d_in[0];
    const int*   idx     = (const int*)d_in[1];
    const float* w_in    = (const float*)d_in[2];
    const float* b_in    = (const float*)d_in[3];
    const float* w1s     = (const float*)d_in[4];
    const float* b1s     = (const float*)d_in[5];
    const float* w2s     = (const float*)d_in[6];
    const float* b2s     = (const float*)d_in[7];
    const float* w_out   = (const float*)d_in[8];
    const float* b_out   = (const float*)d_in[9];
    float* outp = (float*)d_out;

    float *resin, *h, *tmp, *coutb, *al, *ar;
    uint32_t* wfrag;
    cudaGetSymbolAddress((void**)&resin, g_resin);
    cudaGetSymbolAddress((void**)&h,     g_h);
    cudaGetSymbolAddress((void**)&tmp,   g_tmp);
    cudaGetSymbolAddress((void**)&coutb, g_cout);
    cudaGetSymbolAddress((void**)&al,    g_alpha);
    cudaGetSymbolAddress((void**)&ar,    g_araw);
    cudaGetSymbolAddress((void**)&wfrag, g_wfrag);

    // dynamic smem: B + X(324*CIN)
    constexpr int SM_IN  = (18432 + 324 * 32) * 4;   // 115,200
    constexpr int SM_HID = (36864 + 324 * 64) * 4;   // 230,400
    constexpr int SM_OUT = ( 9216 + 324 * 64) * 4;   // 119,808

    cudaFuncSetAttribute(conv_mma<1, 8, true,  false>,
                         cudaFuncAttributeMaxDynamicSharedMemorySize, SM_IN);
    cudaFuncSetAttribute(conv_mma<2, 8, true,  false>,
                         cudaFuncAttributeMaxDynamicSharedMemorySize, SM_HID);
    cudaFuncSetAttribute(conv_mma<2, 8, false, true>,
                         cudaFuncAttributeMaxDynamicSharedMemorySize, SM_HID);
    cudaFuncSetAttribute(conv_mma<2, 2, false, false>,
                         cudaFuncAttributeMaxDynamicSharedMemorySize, SM_OUT);

    wprep_kernel<<<6, 256>>>(w_in, w1s, w2s, w_out, wfrag);
    prep_kernel<<<NIMG, 256>>>(latents, idx, resin, al, ar);

    // conv_in: 25(->32) -> 64, SiLU
    conv_mma<1, 8, true, false><<<NIMG, 256, SM_IN>>>(
        resin, wfrag + WOFF_IN, b_in, h, nullptr);

    for (int blk = 0; blk < 2; blk++) {
        const float* b1 = b1s + blk * 64;
        const float* b2 = b2s + blk * 64;
        conv_mma<2, 8, true, false><<<NIMG, 256, SM_HID>>>(
            h, wfrag + WOFF_HID0 + (2 * blk) * 36864, b1, tmp, nullptr);
        conv_mma<2, 8, false, true><<<NIMG, 256, SM_HID>>>(
            tmp, wfrag + WOFF_HID0 + (2 * blk + 1) * 36864, b2, h, h);
    }

    // conv_out: 64 -> 9(->16)
    conv_mma<2, 2, false, false><<<NIMG, 256, SM_OUT>>>(
        h, wfrag + WOFF_OUT, b_out, coutb, nullptr);

    finalize_kernel<<<NIMG, 256>>>(resin, coutb, al, ar, outp);
}

// round 6
// speedup vs baseline: 1.1870x; 1.1870x over previous
#include <cuda_runtime.h>
#include <cstdint>

#define NIMG 512
#define HW   1024

// ----------------------------------------------------------------------------
// scratch (device globals; no runtime allocation)
// ----------------------------------------------------------------------------
__device__ float    g_resin[(size_t)NIMG * HW * 32];  // NHWC, 25 real ch + pad
__device__ float    g_h[(size_t)NIMG * HW * 64];      // NHWC64
__device__ float    g_tmp[(size_t)NIMG * HW * 64];    // NHWC64
__device__ float    g_cout[(size_t)NIMG * HW * 16];   // NHWC, 9 real ch + pad
__device__ float    g_alpha[NIMG];
__device__ float    g_araw[NIMG];
__device__ uint32_t g_wfrag[18432 + 4 * 36864 + 9216]; // pre-scattered B frags

#define WOFF_IN   0
#define WOFF_HID0 18432
#define WOFF_OUT  (18432 + 4 * 36864)

__device__ __forceinline__ void mma_tf32(float d[4], uint32_t a0, uint32_t a1,
                                         uint32_t a2, uint32_t a3,
                                         uint32_t b0, uint32_t b1) {
    asm volatile(
        "mma.sync.aligned.m16n8k8.row.col.f32.tf32.tf32.f32 "
        "{%0,%1,%2,%3}, {%4,%5,%6,%7}, {%8,%9}, {%0,%1,%2,%3};"
        : "+f"(d[0]), "+f"(d[1]), "+f"(d[2]), "+f"(d[3])
        : "r"(a0), "r"(a1), "r"(a2), "r"(a3), "r"(b0), "r"(b1));
}

__device__ __forceinline__ void cp_async16(uint32_t dst, const void* src, uint32_t srcsize) {
    asm volatile("cp.async.ca.shared.global [%0], [%1], 16, %2;"
                 :: "r"(dst), "l"(src), "r"(srcsize) : "memory");
}
__device__ __forceinline__ void cp_commit() {
    asm volatile("cp.async.commit_group;" ::: "memory");
}
__device__ __forceinline__ void cp_wait0() {
    asm volatile("cp.async.wait_group 0;" ::: "memory");
}
__device__ __forceinline__ uint32_t smem_u32(const void* p) {
    uint32_t a;
    asm("{ .reg .u64 t; cvta.to.shared.u64 t, %1; cvt.u32.u64 %0, t; }"
        : "=r"(a) : "l"(p));
    return a;
}
__device__ __forceinline__ uint32_t f2tf32(float f) {
    uint32_t r;
    asm("cvt.rna.tf32.f32 %0, %1;" : "=r"(r) : "f"(f));
    return r;
}

// ----------------------------------------------------------------------------
// weight prep: natural OIHW -> B-fragment layout.
// Layers 0..4 (NTB=4): [nhalf][chunk][nt4][lane][2]
// Layer 5 (NTB=2):     [chunk][nt2][lane][2]
// k-permutation within each 8-channel group: 2q -> q, 2q+1 -> q+4
// ----------------------------------------------------------------------------
__global__ __launch_bounds__(256)
void wprep_kernel(const float* __restrict__ w_in, const float* __restrict__ w1s,
                  const float* __restrict__ w2s, const float* __restrict__ w_out,
                  uint32_t* __restrict__ wfrag)
{
    const int layer = blockIdx.x;     // 0=in, 1..4=hidden, 5=out
    const int tid = threadIdx.x;

    const float* w;
    int cin, cout, woff, nwords, chunks;
    if (layer == 0)      { w = w_in;  cin = 25; cout = 64; woff = WOFF_IN;  nwords = 18432; chunks = 36; }
    else if (layer <= 4) {
        const int blk = (layer - 1) >> 1;
        w = ((layer - 1) & 1) ? (w2s + (size_t)blk * 64 * 64 * 9)
                              : (w1s + (size_t)blk * 64 * 64 * 9);
        cin = 64; cout = 64; woff = WOFF_HID0 + (layer - 1) * 36864; nwords = 36864; chunks = 72;
    }
    else                 { w = w_out; cin = 64; cout = 9;  woff = WOFF_OUT; nwords = 9216; chunks = 72; }

    for (int i = tid; i < nwords; i += 256) wfrag[woff + i] = 0u;
    __syncthreads();

    const int wtot = cout * cin * 9;
    for (int i = tid; i < wtot; i += 256) {
        const int tap = i % 9;
        const int ci  = (i / 9) % cin;
        const int co  = i / (9 * cin);
        const int cg  = ci >> 5;
        const int kin = ci & 31;
        const int w8  = kin & 7;
        const int kkp = (kin & 24) | (w8 >> 1) | ((w8 & 1) << 2);
        const int kg  = (cg * 9 + tap) * 32 + kkp;
        const int chunk = kg >> 3;
        const int kk    = kg & 7;
        const int h     = kk >> 2;
        const int bl    = ((co & 7) << 2) | (kk & 3);
        const int nt    = co >> 3;
        int word;
        if (layer <= 4) {
            const int nhalf = nt >> 2;
            const int nt4   = nt & 3;
            word = woff + nhalf * chunks * 256 + (chunk * 4 + nt4) * 64 + bl * 2 + h;
        } else {
            word = woff + (chunk * 2 + nt) * 64 + bl * 2 + h;
        }
        wfrag[word] = f2tf32(w[i]);
    }
}

// ----------------------------------------------------------------------------
// prep: keyframe lerp -> NHWC32 res_in
// ----------------------------------------------------------------------------
__global__ __launch_bounds__(256)
void prep_kernel(const float* __restrict__ latents, const int* __restrict__ idx,
                 float* __restrict__ resin, float* __restrict__ alpha_arr,
                 float* __restrict__ araw_arr)
{
    const int n = blockIdx.x;
    const int b = n >> 7;
    const int t = n & 127;

    int v[9];
#pragma unroll
    for (int k = 0; k < 9; k++) v[k] = idx[b * 9 + k];
#pragma unroll
    for (int i = 1; i < 9; i++) {
        int key = v[i]; int j = i - 1;
        while (j >= 0 && v[j] > key) { v[j + 1] = v[j]; j--; }
        v[j + 1] = key;
    }
    int cnt = 0;
#pragma unroll
    for (int k = 0; k < 9; k++) cnt += (v[k] <= t);
    int seg = min(max(cnt - 1, 0), 7);
    const int t0 = v[seg], t1 = v[seg + 1];
    const float araw = (float)(t - t0) / (float)max(t1 - t0, 1);
    const float a = fminf(fmaxf(araw, 0.f), 1.f);

    const int tid = threadIdx.x;
    const float* L0 = latents + ((size_t)(b * 128 + t0)) * 8 * HW;
    const float* L1 = latents + ((size_t)(b * 128 + t1)) * 8 * HW;
    float* R = resin + (size_t)n * HW * 32;

#pragma unroll
    for (int j = 0; j < 4; j++) {
        const int p = tid + 256 * j;
        float buf[32];
#pragma unroll
        for (int c = 0; c < 8; c++) {
            const float z0 = L0[c * HW + p];
            const float z1 = L1[c * HW + p];
            buf[c]      = (1.f - a) * z0 + a * z1;
            buf[8 + c]  = z0;
            buf[16 + c] = z1;
        }
        buf[24] = a;
#pragma unroll
        for (int c = 25; c < 32; c++) buf[c] = 0.f;
        float4* dst = (float4*)(R + (size_t)p * 32);
#pragma unroll
        for (int q = 0; q < 8; q++)
            dst[q] = make_float4(buf[q*4], buf[q*4+1], buf[q*4+2], buf[q*4+3]);
    }
    if (tid == 0) { alpha_arr[n] = a; araw_arr[n] = araw; }
}

// ----------------------------------------------------------------------------
// implicit-GEMM 3x3 SAME conv, mma.sync m16n8k8 tf32.
// Per-warp tile M64 (2 rows x 32 cols) x N = NTB*8.
// Grid (512, 2) for 64-out layers (N split across 2 CTAs), (512,1) for out layer.
// X staged per 8-channel slice: [612 px][8 words] -> conflict-free LDS.64 with
// pure immediate offsets. 2 CTAs/SM.
// ----------------------------------------------------------------------------
template<int CG, int NTB, bool SILU, bool RESID>
__global__ __launch_bounds__(256, 2)
void conv_mma(const float* __restrict__ in, const uint32_t* __restrict__ wfrag,
              const float* __restrict__ bias, float* __restrict__ out,
              const float* __restrict__ resid)
{
    constexpr int CIN    = CG * 32;
    constexpr int COUT   = (NTB == 4) ? 64 : 16;
    constexpr int CHUNKS = CG * 36;
    constexpr int BW     = CHUNKS * NTB * 64;   // B words
    constexpr int NST    = CG * 4;              // 8-ch stages per tile

    extern __shared__ uint32_t smem[];
    uint32_t* b_s = smem;            // BW words
    uint32_t* X_s = smem + BW;       // 612*8 = 4896 words

    const int tid   = threadIdx.x;
    const int wid   = tid >> 5;
    const int lane  = tid & 31;
    const int n     = blockIdx.x;
    const int nhalf = blockIdx.y;
    const int tx    = lane >> 2;
    const int kq2   = (lane & 3) * 2;
    const int ch0   = (NTB == 4) ? nhalf * 32 : 0;

    const uint32_t bs_u = smem_u32(b_s);
    const uint32_t xs_u = smem_u32(X_s);

    // ---- stage B fragments (once); completion folded into first X wait ----
    const uint32_t* wsrc = wfrag + (size_t)nhalf * CHUNKS * 4 * 64;  // nhalf=0 if NTB==2
    for (int i = tid; i < BW / 4; i += 256)
        cp_async16(bs_u + i * 16, wsrc + i * 4, 16);

    // bias -> registers
    float bv[NTB][2];
#pragma unroll
    for (int nt = 0; nt < NTB; nt++) {
        const int bi = ch0 + nt * 8 + kq2;
        bv[nt][0] = (NTB == 4 || bi     < 9) ? bias[bi]     : 0.f;
        bv[nt][1] = (NTB == 4 || bi + 1 < 9) ? bias[bi + 1] : 0.f;
    }

#pragma unroll 1
    for (int tile = 0; tile < 2; tile++) {
        const int y0 = tile * 16;

        float d[4][NTB][4];
#pragma unroll
        for (int f = 0; f < 4; f++)
#pragma unroll
            for (int nt = 0; nt < NTB; nt++)
#pragma unroll
                for (int q = 0; q < 4; q++) d[f][nt][q] = 0.f;

#pragma unroll 1
        for (int s = 0; s < NST; s++) {
            if (tile | s) __syncthreads();           // X fully consumed
            const int cg  = (CG == 2) ? (s >> 2) : 0;
            const int oct = s & 3;

            // ---- stage 18x34 window, 8 channels ----
            for (int i = tid; i < 1224; i += 256) {
                const int px   = i >> 1;
                const int part = i & 1;
                const int rr   = px / 34;
                const int cc   = px - rr * 34;
                const int gy   = y0 - 1 + rr;
                const int gx   = cc - 1;
                const bool ok  = (gy >= 0) && (gy < 32) && (gx >= 0) && (gx < 32);
                const float* src = in + ((size_t)n * HW + (ok ? gy * 32 + gx : 0)) * CIN
                                   + cg * 32 + oct * 8 + part * 4;
                cp_async16(xs_u + (px * 8 + part * 4) * 4, src, ok ? 16u : 0u);
            }
            cp_commit();
            cp_wait0();
            __syncthreads();

            const int cbase = (cg * 9) * 4 + oct;

#pragma unroll
            for (int tap = 0; tap < 9; tap++) {
                const int dy = tap / 3, dx = tap - 3 * (tap / 3);
                const uint32_t* A = X_s + ((2 * wid + dy) * 34 + tx + dx) * 8 + kq2;
                const uint2 u0 = *(const uint2*)(A);          // row r,   cols +0..15 (px tx)
                const uint2 u1 = *(const uint2*)(A + 64);     //          (px tx+8)
                const uint2 u2 = *(const uint2*)(A + 128);    // row r,   cols +16..31
                const uint2 u3 = *(const uint2*)(A + 192);
                const uint2 u4 = *(const uint2*)(A + 272);    // row r+1, cols +0..15
                const uint2 u5 = *(const uint2*)(A + 336);
                const uint2 u6 = *(const uint2*)(A + 400);    // row r+1, cols +16..31
                const uint2 u7 = *(const uint2*)(A + 464);
                const uint32_t* bp = b_s + (size_t)(cbase + tap * 4) * NTB * 64 + lane * 2;
#pragma unroll
                for (int nt = 0; nt < NTB; nt++) {
                    const uint2 b = *(const uint2*)(bp + nt * 64);
                    mma_tf32(d[0][nt], u0.x, u1.x, u0.y, u1.y, b.x, b.y);
                    mma_tf32(d[1][nt], u2.x, u3.x, u2.y, u3.y, b.x, b.y);
                    mma_tf32(d[2][nt], u4.x, u5.x, u4.y, u5.y, b.x, b.y);
                    mma_tf32(d[3][nt], u6.x, u7.x, u6.y, u7.y, b.x, b.y);
                }
            }
        }

        // ---- epilogue: 4 fragments per warp ----
#pragma unroll
        for (int f = 0; f < 4; f++) {
            const int gy = y0 + 2 * wid + (f >> 1);
            const int gx = ((f & 1) << 4) + tx;
            const size_t gp0 = (size_t)n * HW + gy * 32 + gx;
            const size_t gp1 = gp0 + 8;
#pragma unroll
            for (int nt = 0; nt < NTB; nt++) {
                const int c = ch0 + nt * 8 + kq2;
                float v00 = d[f][nt][0] + bv[nt][0];
                float v01 = d[f][nt][1] + bv[nt][1];
                float v10 = d[f][nt][2] + bv[nt][0];
                float v11 = d[f][nt][3] + bv[nt][1];
                if (SILU) {
                    v00 = v00 / (1.f + __expf(-v00));
                    v01 = v01 / (1.f + __expf(-v01));
                    v10 = v10 / (1.f + __expf(-v10));
                    v11 = v11 / (1.f + __expf(-v11));
                }
                if (RESID) {
                    const float2 r0 = *(const float2*)(resid + gp0 * COUT + c);
                    const float2 r1 = *(const float2*)(resid + gp1 * COUT + c);
                    v00 += r0.x; v01 += r0.y; v10 += r1.x; v11 += r1.y;
                }
                *(float2*)(out + gp0 * COUT + c) = make_float2(v00, v01);
                *(float2*)(out + gp1 * COUT + c) = make_float2(v10, v11);
            }
        }
    }
}

// ----------------------------------------------------------------------------
// finalize: z_hat (NCHW) + conf
// ----------------------------------------------------------------------------
__global__ __launch_bounds__(256)
void finalize_kernel(const float* __restrict__ resin, const float* __restrict__ co,
                     const float* __restrict__ alpha_arr, const float* __restrict__ araw_arr,
                     float* __restrict__ outp)
{
    const int n = blockIdx.x;
    const int tid = threadIdx.x;
    const float a  = alpha_arr[n];
    const float ar = araw_arr[n];
    const float s  = a * (1.f - a);
    const bool interior = (ar > 0.f) && (ar < 1.f);

#pragma unroll
    for (int j = 0; j < 4; j++) {
        const int p = tid + 256 * j;
        const float* R = resin + ((size_t)n * HW + p) * 32;
        const float* O = co + ((size_t)n * HW + p) * 16;
        float zb[8], res[9];
#pragma unroll
        for (int c = 0; c < 8; c++) zb[c] = R[c];
#pragma unroll
        for (int c = 0; c < 9; c++) res[c] = O[c];
#pragma unroll
        for (int c = 0; c < 8; c++)
            outp[((size_t)n * 8 + c) * HW + p] = zb[c] + s * res[c];
        const float unc = 1.f / (1.f + __expf(-res[8]));
        outp[(size_t)NIMG * 8 * HW + (size_t)n * HW + p] =
            interior ? fminf(fmaxf(1.f - unc, 0.f), 1.f) : 1.f;
    }
}

// ----------------------------------------------------------------------------
// launch
// ----------------------------------------------------------------------------
extern "C" void kernel_launch(void* const* d_in, const int* in_sizes, int n_in,
                              void* d_out, int out_size)
{
    const float* latents = (const float*)d_in[0];
    const int*   idx     = (const int*)d_in[1];
    const float* w_in    = (const float*)d_in[2];
    const float* b_in    = (const float*)d_in[3];
    const float* w1s     = (const float*)d_in[4];
    const float* b1s     = (const float*)d_in[5];
    const float* w2s     = (const float*)d_in[6];
    const float* b2s     = (const float*)d_in[7];
    const float* w_out   = (const float*)d_in[8];
    const float* b_out   = (const float*)d_in[9];
    float* outp = (float*)d_out;

    float *resin, *h, *tmp, *coutb, *al, *ar;
    uint32_t* wfrag;
    cudaGetSymbolAddress((void**)&resin, g_resin);
    cudaGetSymbolAddress((void**)&h,     g_h);
    cudaGetSymbolAddress((void**)&tmp,   g_tmp);
    cudaGetSymbolAddress((void**)&coutb, g_cout);
    cudaGetSymbolAddress((void**)&al,    g_alpha);
    cudaGetSymbolAddress((void**)&ar,    g_araw);
    cudaGetSymbolAddress((void**)&wfrag, g_wfrag);

    // dynamic smem: B + X(612*8 words = 19,584B)
    constexpr int SM_IN  = ( 9216 + 4896) * 4;   // 56,448
    constexpr int SM_HID = (18432 + 4896) * 4;   // 93,312
    constexpr int SM_OUT = ( 9216 + 4896) * 4;   // 56,448

    cudaFuncSetAttribute(conv_mma<1, 4, true,  false>,
                         cudaFuncAttributeMaxDynamicSharedMemorySize, SM_IN);
    cudaFuncSetAttribute(conv_mma<2, 4, true,  false>,
                         cudaFuncAttributeMaxDynamicSharedMemorySize, SM_HID);
    cudaFuncSetAttribute(conv_mma<2, 4, false, true>,
                         cudaFuncAttributeMaxDynamicSharedMemorySize, SM_HID);
    cudaFuncSetAttribute(conv_mma<2, 2, false, false>,
                         cudaFuncAttributeMaxDynamicSharedMemorySize, SM_OUT);

    wprep_kernel<<<6, 256>>>(w_in, w1s, w2s, w_out, wfrag);
    prep_kernel<<<NIMG, 256>>>(latents, idx, resin, al, ar);

    // conv_in: 25(->32) -> 64, SiLU   (N split across 2 CTAs)
    conv_mma<1, 4, true, false><<<dim3(NIMG, 2), 256, SM_IN>>>(
        resin, wfrag + WOFF_IN, b_in, h, nullptr);

    for (int blk = 0; blk < 2; blk++) {
        const float* b1 = b1s + blk * 64;
        const float* b2 = b2s + blk * 64;
        conv_mma<2, 4, true, false><<<dim3(NIMG, 2), 256, SM_HID>>>(
            h, wfrag + WOFF_HID0 + (2 * blk) * 36864, b1, tmp, nullptr);
        conv_mma<2, 4, false, true><<<dim3(NIMG, 2), 256, SM_HID>>>(
            tmp, wfrag + WOFF_HID0 + (2 * blk + 1) * 36864, b2, h, h);
    }

    // conv_out: 64 -> 9(->16)
    conv_mma<2, 2, false, false><<<dim3(NIMG, 1), 256, SM_OUT>>>(
        h, wfrag + WOFF_OUT, b_out, coutb, nullptr);

    finalize_kernel<<<NIMG, 256>>>(resin, coutb, al, ar, outp);
}

// round 7
// speedup vs baseline: 2.1310x; 1.7952x over previous
#include <cuda_runtime.h>
#include <cuda_fp16.h>
#include <cstdint>
#include <cstring>

#define NIMG 512
#define HW   1024

// ----------------------------------------------------------------------------
// scratch (device globals; no runtime allocation)
// ----------------------------------------------------------------------------
__device__ __half    g_resin[(size_t)NIMG * HW * 32];  // fp16 NHWC32 (permuted)
__device__ __half    g_h[(size_t)NIMG * HW * 64];      // fp16 NHWC64 (permuted)
__device__ __half    g_tmp[(size_t)NIMG * HW * 64];    // fp16 NHWC64 (permuted)
__device__ float     g_cout[(size_t)NIMG * HW * 16];   // fp32 NHWC16 (unpermuted)
__device__ uint32_t  g_wfrag[131072];                  // pre-scattered B frags (f16x2)

// wfrag word offsets
#define WOFF_IN   0
#define WOFF_HID0 9216
#define WOFF_OUT  (9216 + 4 * 18432)   // 82944

__device__ __forceinline__ void mma_f16(float d[4], uint32_t a0, uint32_t a1,
                                        uint32_t a2, uint32_t a3,
                                        uint32_t b0, uint32_t b1) {
    asm volatile(
        "mma.sync.aligned.m16n8k16.row.col.f32.f16.f16.f32 "
        "{%0,%1,%2,%3}, {%4,%5,%6,%7}, {%8,%9}, {%0,%1,%2,%3};"
        : "+f"(d[0]), "+f"(d[1]), "+f"(d[2]), "+f"(d[3])
        : "r"(a0), "r"(a1), "r"(a2), "r"(a3), "r"(b0), "r"(b1));
}

__device__ __forceinline__ void cp_async16(uint32_t dst, const void* src, uint32_t srcsize) {
    asm volatile("cp.async.ca.shared.global [%0], [%1], 16, %2;"
                 :: "r"(dst), "l"(src), "r"(srcsize) : "memory");
}
__device__ __forceinline__ void cp_commit() {
    asm volatile("cp.async.commit_group;" ::: "memory");
}
__device__ __forceinline__ void cp_wait0() {
    asm volatile("cp.async.wait_group 0;" ::: "memory");
}
__device__ __forceinline__ uint32_t smem_u32(const void* p) {
    uint32_t a;
    asm("{ .reg .u64 t; cvta.to.shared.u64 t, %1; cvt.u32.u64 %0, t; }"
        : "=r"(a) : "l"(p));
    return a;
}
__device__ __forceinline__ uint32_t h2u(__half2 h) {
    uint32_t u; memcpy(&u, &h, 4); return u;
}

// ----------------------------------------------------------------------------
// weight prep: OIHW fp32 -> f16 B-fragment layout (one-time, 6 blocks).
// Channel permutation inside each 16-group matches X storage:
// storage pos j holds channel c(j) = ((j>>1)&3)*2 + (j&1)*8  (pairs stay adjacent)
// equivalently MMA k index == channel index. Fragment word layout:
//   NTB=4 layers: [nhalf][chunk][nt4][lane][2] ; NTB=2: [chunk][nt2][lane][2]
// chunk = (cg*9 + tap)*2 + (kin>>4)
// ----------------------------------------------------------------------------
__global__ __launch_bounds__(256)
void wprep_kernel(const float* __restrict__ w_in, const float* __restrict__ w1s,
                  const float* __restrict__ w2s, const float* __restrict__ w_out,
                  uint32_t* __restrict__ wfrag)
{
    const int layer = blockIdx.x;     // 0=in, 1..4=hidden, 5=out
    const int tid = threadIdx.x;

    const float* w;
    int cin, cout, woff, nwords, chunks, ntb;
    if (layer == 0)      { w = w_in;  cin = 25; cout = 64; woff = WOFF_IN;  nwords = 9216;  chunks = 18; ntb = 4; }
    else if (layer <= 4) {
        const int blk = (layer - 1) >> 1;
        w = ((layer - 1) & 1) ? (w2s + (size_t)blk * 64 * 64 * 9)
                              : (w1s + (size_t)blk * 64 * 64 * 9);
        cin = 64; cout = 64; woff = WOFF_HID0 + (layer - 1) * 18432; nwords = 18432; chunks = 36; ntb = 4;
    }
    else                 { w = w_out; cin = 64; cout = 9;  woff = WOFF_OUT; nwords = 4608; chunks = 36; ntb = 2; }

    for (int i = tid; i < nwords; i += 256) wfrag[woff + i] = 0u;
    __syncthreads();

    __half* wh = (__half*)(wfrag);
    const int wtot = cout * cin * 9;
    for (int i = tid; i < wtot; i += 256) {
        const int tap = i % 9;
        const int ci  = (i / 9) % cin;
        const int co  = i / (9 * cin);
        const int cg  = ci >> 5;
        const int kin = ci & 31;
        const int g2  = kin >> 4;
        const int k16 = kin & 15;
        const int chunk = (cg * 9 + tap) * 2 + g2;
        const int hi  = k16 >> 3;
        const int rem = k16 & 7;
        const int tt  = rem >> 1;
        const int hf  = rem & 1;
        const int lane = (co & 7) * 4 + tt;
        int word;
        if (ntb == 4) {
            const int nhalf = co >> 5;
            const int nt4   = (co >> 3) & 3;
            word = woff + nhalf * chunks * 256 + (chunk * 4 + nt4) * 64 + lane * 2 + hi;
        } else {
            const int nt = co >> 3;
            word = woff + (chunk * 2 + nt) * 64 + lane * 2 + hi;
        }
        wh[word * 2 + hf] = __float2half(w[i]);
    }
}

// ----------------------------------------------------------------------------
// prep: keyframe lerp -> fp16 permuted NHWC32 res_in
// ----------------------------------------------------------------------------
__global__ __launch_bounds__(256)
void prep_kernel(const float* __restrict__ latents, const int* __restrict__ idx,
                 __half* __restrict__ resin)
{
    const int n = blockIdx.x;
    const int b = n >> 7;
    const int t = n & 127;

    int v[9];
#pragma unroll
    for (int k = 0; k < 9; k++) v[k] = idx[b * 9 + k];
#pragma unroll
    for (int i = 1; i < 9; i++) {
        int key = v[i]; int j = i - 1;
        while (j >= 0 && v[j] > key) { v[j + 1] = v[j]; j--; }
        v[j + 1] = key;
    }
    int cnt = 0;
#pragma unroll
    for (int k = 0; k < 9; k++) cnt += (v[k] <= t);
    int seg = min(max(cnt - 1, 0), 7);
    const int t0 = v[seg], t1 = v[seg + 1];
    const float araw = (float)(t - t0) / (float)max(t1 - t0, 1);
    const float a = fminf(fmaxf(araw, 0.f), 1.f);

    const int tid = threadIdx.x;
    const float* L0 = latents + ((size_t)(b * 128 + t0)) * 8 * HW;
    const float* L1 = latents + ((size_t)(b * 128 + t1)) * 8 * HW;

#pragma unroll
    for (int j = 0; j < 4; j++) {
        const int p = tid + 256 * j;
        float buf[32];
#pragma unroll
        for (int c = 0; c < 8; c++) {
            const float z0 = L0[c * HW + p];
            const float z1 = L1[c * HW + p];
            buf[c]      = (1.f - a) * z0 + a * z1;
            buf[8 + c]  = z0;
            buf[16 + c] = z1;
        }
        buf[24] = a;
#pragma unroll
        for (int c = 25; c < 32; c++) buf[c] = 0.f;

        // permuted fp16 store: word j holds channels (g*16 + cl, +1),
        // cl = ((j&7)>>1 & 3)*2 + ((j&1))*8  -- see c(j) map
        uint32_t wds[16];
#pragma unroll
        for (int g = 0; g < 2; g++)
#pragma unroll
            for (int jj = 0; jj < 8; jj++) {
                const int cl = ((jj >> 1) & 3) * 2 + (jj & 1) * 8;
                const int c  = g * 16 + cl;
                wds[g * 8 + jj] = h2u(__floats2half2_rn(buf[c], buf[c + 1]));
            }
        uint4* dst = (uint4*)(resin + ((size_t)n * HW + p) * 32);
#pragma unroll
        for (int q = 0; q < 4; q++)
            dst[q] = make_uint4(wds[q*4], wds[q*4+1], wds[q*4+2], wds[q*4+3]);
    }
}

// ----------------------------------------------------------------------------
// implicit-GEMM 3x3 SAME conv, mma.sync m16n8k16 fp16 (fp32 accum).
// Per-warp tile M64 x N = NTB*8. Grid (512,2) for 64-out layers.
// X staged per 16-channel slab: [612 px][8 words(32B)], conflict-free LDS.64,
// pure immediate offsets. CG rounds per tile, 2 slabs per round. 2 CTAs/SM.
// ----------------------------------------------------------------------------
template<int CG, int NTB, bool SILU, bool RESID>
__global__ __launch_bounds__(256, 2)
void conv_mma(const void* __restrict__ in_v, const uint32_t* __restrict__ wfrag,
              const float* __restrict__ bias, void* __restrict__ out_v,
              const void* __restrict__ resid_v)
{
    constexpr int CIN    = CG * 32;              // halves per pixel
    constexpr int CHUNKS = CG * 18;
    constexpr int BW     = CHUNKS * NTB * 64;    // B words
    constexpr bool F16OUT = (NTB == 4);

    extern __shared__ uint32_t smem[];
    uint32_t* b_s = smem;            // BW words
    uint32_t* X_s = smem + BW;       // 2 slabs * 4896 words

    const int tid   = threadIdx.x;
    const int wid   = tid >> 5;
    const int lane  = tid & 31;
    const int n     = blockIdx.x;
    const int nhalf = blockIdx.y;
    const int tx    = lane >> 2;
    const int kq2   = (lane & 3) * 2;            // word offset within pixel
    const int ch0   = F16OUT ? nhalf * 32 : 0;

    const uint32_t bs_u = smem_u32(b_s);
    const uint32_t xs_u = smem_u32(X_s);
    const char* in_b = (const char*)in_v + (size_t)n * HW * CIN * 2;

    // ---- stage B fragments (once) ----
    const uint32_t* wsrc = wfrag + (size_t)nhalf * CHUNKS * NTB * 64;
    for (int i = tid; i < BW / 4; i += 256)
        cp_async16(bs_u + i * 16, wsrc + i * 4, 16);

    // bias -> registers
    float bv[NTB][2];
#pragma unroll
    for (int nt = 0; nt < NTB; nt++) {
        const int bi = ch0 + nt * 8 + kq2;
        bv[nt][0] = (F16OUT || bi     < 9) ? bias[bi]     : 0.f;
        bv[nt][1] = (F16OUT || bi + 1 < 9) ? bias[bi + 1] : 0.f;
    }

    // tile-invariant staging slot dst
    uint32_t s_dst[10];
#pragma unroll
    for (int k = 0; k < 10; k++) {
        const int i = tid + k * 256;
        const int px = i >> 2, sub = i & 3;
        s_dst[k] = (uint32_t)(((sub >> 1) * 4896 + px * 8 + (sub & 1) * 4) * 4);
    }

#pragma unroll 1
    for (int tile = 0; tile < 2; tile++) {
        // per-tile slot sources
        int s_src[10]; uint32_t okb = 0;
#pragma unroll
        for (int k = 0; k < 10; k++) {
            const int i = tid + k * 256;
            const int px = (i >> 2), sub = i & 3;
            const int slab = sub >> 1, part = sub & 1;
            const int rr = px / 34;
            const int gx = px - rr * 34 - 1;
            const int gy = tile * 16 - 1 + rr;
            const bool ok = (gx >= 0) && (gx < 32) && (gy >= 0) && (gy < 32) && (i < 2448);
            const int pix = ok ? (gy * 32 + gx) : 0;
            s_src[k] = (pix * CIN + part * 8) * 2 + slab * 32;
            okb |= (ok ? 1u : 0u) << k;
        }

        float d[4][NTB][4];
#pragma unroll
        for (int f = 0; f < 4; f++)
#pragma unroll
            for (int nt = 0; nt < NTB; nt++)
#pragma unroll
                for (int q = 0; q < 4; q++) d[f][nt][q] = 0.f;

#pragma unroll 1
        for (int r = 0; r < CG; r++) {
            if (tile | r) __syncthreads();
            // ---- stage two 16-ch slabs ----
#pragma unroll
            for (int k = 0; k < 10; k++) {
                if (k < 9 || tid < 144)
                    cp_async16(xs_u + s_dst[k], in_b + s_src[k] + r * 64,
                               ((okb >> k) & 1) ? 16u : 0u);
            }
            cp_commit();
            cp_wait0();
            __syncthreads();

#pragma unroll
            for (int slab = 0; slab < 2; slab++) {
                const uint32_t* Xb = X_s + slab * 4896;
                const int cb = r * 18 + slab;       // chunk = cb + tap*2
#pragma unroll
                for (int tap = 0; tap < 9; tap++) {
                    const int dy = tap / 3, dx = tap - 3 * (tap / 3);
                    const uint32_t* A = Xb + ((2 * wid + dy) * 34 + tx + dx) * 8 + kq2;
                    const uint2 u0 = *(const uint2*)(A);          // row r,   px tx
                    const uint2 u1 = *(const uint2*)(A + 64);     //          px tx+8
                    const uint2 u2 = *(const uint2*)(A + 128);    //          px tx+16
                    const uint2 u3 = *(const uint2*)(A + 192);    //          px tx+24
                    const uint2 u4 = *(const uint2*)(A + 272);    // row r+1, px tx
                    const uint2 u5 = *(const uint2*)(A + 336);
                    const uint2 u6 = *(const uint2*)(A + 400);
                    const uint2 u7 = *(const uint2*)(A + 464);
                    const uint32_t* bp = b_s + (size_t)(cb + tap * 2) * NTB * 64 + lane * 2;
#pragma unroll
                    for (int nt = 0; nt < NTB; nt++) {
                        const uint2 b = *(const uint2*)(bp + nt * 64);
                        mma_f16(d[0][nt], u0.x, u1.x, u0.y, u1.y, b.x, b.y);
                        mma_f16(d[1][nt], u2.x, u3.x, u2.y, u3.y, b.x, b.y);
                        mma_f16(d[2][nt], u4.x, u5.x, u4.y, u5.y, b.x, b.y);
                        mma_f16(d[3][nt], u6.x, u7.x, u6.y, u7.y, b.x, b.y);
                    }
                }
            }
        }

        // ---- epilogue ----
#pragma unroll
        for (int f = 0; f < 4; f++) {
            const int gy = tile * 16 + 2 * wid + (f >> 1);
            const int gx = ((f & 1) << 4) + tx;
            const size_t gp0 = (size_t)n * HW + gy * 32 + gx;
            const size_t gp1 = gp0 + 8;
#pragma unroll
            for (int nt = 0; nt < NTB; nt++) {
                const int c = ch0 + nt * 8 + kq2;
                float v00 = d[f][nt][0] + bv[nt][0];
                float v01 = d[f][nt][1] + bv[nt][1];
                float v10 = d[f][nt][2] + bv[nt][0];
                float v11 = d[f][nt][3] + bv[nt][1];
                if (SILU) {
                    v00 = __fdividef(v00, 1.f + __expf(-v00));
                    v01 = __fdividef(v01, 1.f + __expf(-v01));
                    v10 = __fdividef(v10, 1.f + __expf(-v10));
                    v11 = __fdividef(v11, 1.f + __expf(-v11));
                }
                if (F16OUT) {
                    // permuted fp16 NHWC64 store
                    const int g16 = c >> 4;
                    const int cl  = c & 15;
                    const int jl  = (((cl >> 3) & 1) << 1) | (((cl >> 1) & 3) << 2);
                    const size_t h0 = gp0 * 64 + g16 * 16 + jl;
                    const size_t h1 = gp1 * 64 + g16 * 16 + jl;
                    if (RESID) {
                        const __half2* rh = (const __half2*)resid_v;
                        const float2 r0 = __half22float2(rh[h0 >> 1]);
                        const float2 r1 = __half22float2(rh[h1 >> 1]);
                        v00 += r0.x; v01 += r0.y; v10 += r1.x; v11 += r1.y;
                    }
                    __half2* oh = (__half2*)out_v;
                    oh[h0 >> 1] = __floats2half2_rn(v00, v01);
                    oh[h1 >> 1] = __floats2half2_rn(v10, v11);
                } else {
                    float* of = (float*)out_v;
                    *(float2*)(of + gp0 * 16 + c) = make_float2(v00, v01);
                    *(float2*)(of + gp1 * 16 + c) = make_float2(v10, v11);
                }
            }
        }
    }
}

// ----------------------------------------------------------------------------
// finalize: recompute fp32 z_base from latents; z_hat (NCHW) + conf
// ----------------------------------------------------------------------------
__global__ __launch_bounds__(256)
void finalize_kernel(const float* __restrict__ latents, const int* __restrict__ idx,
                     const float* __restrict__ co, float* __restrict__ outp)
{
    const int n = blockIdx.x;
    const int b = n >> 7;
    const int t = n & 127;

    int v[9];
#pragma unroll
    for (int k = 0; k < 9; k++) v[k] = idx[b * 9 + k];
#pragma unroll
    for (int i = 1; i < 9; i++) {
        int key = v[i]; int j = i - 1;
        while (j >= 0 && v[j] > key) { v[j + 1] = v[j]; j--; }
        v[j + 1] = key;
    }
    int cnt = 0;
#pragma unroll
    for (int k = 0; k < 9; k++) cnt += (v[k] <= t);
    int seg = min(max(cnt - 1, 0), 7);
    const int t0 = v[seg], t1 = v[seg + 1];
    const float araw = (float)(t - t0) / (float)max(t1 - t0, 1);
    const float a = fminf(fmaxf(araw, 0.f), 1.f);
    const float s = a * (1.f - a);
    const bool interior = (araw > 0.f) && (araw < 1.f);

    const int tid = threadIdx.x;
    const float* L0 = latents + ((size_t)(b * 128 + t0)) * 8 * HW;
    const float* L1 = latents + ((size_t)(b * 128 + t1)) * 8 * HW;

#pragma unroll
    for (int j = 0; j < 4; j++) {
        const int p = tid + 256 * j;
        const float* O = co + ((size_t)n * HW + p) * 16;
#pragma unroll
        for (int c = 0; c < 8; c++) {
            const float z0 = L0[c * HW + p];
            const float z1 = L1[c * HW + p];
            const float zb = (1.f - a) * z0 + a * z1;
            outp[((size_t)n * 8 + c) * HW + p] = zb + s * O[c];
        }
        const float unc = __fdividef(1.f, 1.f + __expf(-O[8]));
        outp[(size_t)NIMG * 8 * HW + (size_t)n * HW + p] =
            interior ? fminf(fmaxf(1.f - unc, 0.f), 1.f) : 1.f;
    }
}

// ----------------------------------------------------------------------------
// launch
// ----------------------------------------------------------------------------
extern "C" void kernel_launch(void* const* d_in, const int* in_sizes, int n_in,
                              void* d_out, int out_size)
{
    const float* latents = (const float*)d_in[0];
    const int*   idx     = (const int*)d_in[1];
    const float* w_in    = (const float*)d_in[2];
    const float* b_in    = (const float*)d_in[3];
    const float* w1s     = (const float*)d_in[4];
    const float* b1s     = (const float*)d_in[5];
    const float* w2s     = (const float*)d_in[6];
    const float* b2s     = (const float*)d_in[7];
    const float* w_out   = (const float*)d_in[8];
    const float* b_out   = (const float*)d_in[9];
    float* outp = (float*)d_out;

    __half *resin, *h, *tmp;
    float *coutb;
    uint32_t* wfrag;
    cudaGetSymbolAddress((void**)&resin, g_resin);
    cudaGetSymbolAddress((void**)&h,     g_h);
    cudaGetSymbolAddress((void**)&tmp,   g_tmp);
    cudaGetSymbolAddress((void**)&coutb, g_cout);
    cudaGetSymbolAddress((void**)&wfrag, g_wfrag);

    // dynamic smem: B + 2 X slabs (2*4896 words)
    constexpr int SM_IN  = ( 4608 + 9792) * 4;   // 57,600
    constexpr int SM_HID = ( 9216 + 9792) * 4;   // 76,032
    constexpr int SM_OUT = ( 4608 + 9792) * 4;   // 57,600

    cudaFuncSetAttribute(conv_mma<1, 4, true,  false>,
                         cudaFuncAttributeMaxDynamicSharedMemorySize, SM_IN);
    cudaFuncSetAttribute(conv_mma<2, 4, true,  false>,
                         cudaFuncAttributeMaxDynamicSharedMemorySize, SM_HID);
    cudaFuncSetAttribute(conv_mma<2, 4, false, true>,
                         cudaFuncAttributeMaxDynamicSharedMemorySize, SM_HID);
    cudaFuncSetAttribute(conv_mma<2, 2, false, false>,
                         cudaFuncAttributeMaxDynamicSharedMemorySize, SM_OUT);

    wprep_kernel<<<6, 256>>>(w_in, w1s, w2s, w_out, wfrag);
    prep_kernel<<<NIMG, 256>>>(latents, idx, resin);

    // conv_in: 25(->32) -> 64, SiLU   (N split across 2 CTAs)
    conv_mma<1, 4, true, false><<<dim3(NIMG, 2), 256, SM_IN>>>(
        resin, wfrag + WOFF_IN, b_in, h, nullptr);

    for (int blk = 0; blk < 2; blk++) {
        const float* b1 = b1s + blk * 64;
        const float* b2 = b2s + blk * 64;
        conv_mma<2, 4, true, false><<<dim3(NIMG, 2), 256, SM_HID>>>(
            h, wfrag + WOFF_HID0 + (2 * blk) * 18432, b1, tmp, nullptr);
        conv_mma<2, 4, false, true><<<dim3(NIMG, 2), 256, SM_HID>>>(
            tmp, wfrag + WOFF_HID0 + (2 * blk + 1) * 18432, b2, h, h);
    }

    // conv_out: 64 -> 9(->16), fp32 out
    conv_mma<2, 2, false, false><<<dim3(NIMG, 1), 256, SM_OUT>>>(
        h, wfrag + WOFF_OUT, b_out, coutb, nullptr);

    finalize_kernel<<<NIMG, 256>>>(latents, idx, coutb, outp);
}

// round 8
// speedup vs baseline: 2.1898x; 1.0276x over previous
#include <cuda_runtime.h>
#include <cuda_fp16.h>
#include <cstdint>
#include <cstring>

#define NIMG 512
#define HW   1024

// ----------------------------------------------------------------------------
// scratch (device globals; no runtime allocation)
// ----------------------------------------------------------------------------
__device__ __half    g_resin[(size_t)NIMG * HW * 32];  // fp16 NHWC32 (permuted)
__device__ __half    g_h[(size_t)NIMG * HW * 64];      // fp16 NHWC64 (permuted)
__device__ __half    g_tmp[(size_t)NIMG * HW * 64];    // fp16 NHWC64 (permuted)
__device__ float     g_cout[(size_t)NIMG * HW * 16];   // fp32 NHWC16 (unpermuted)
__device__ uint32_t  g_wfrag[131072];                  // pre-scattered B frags (f16x2)

// wfrag word offsets
#define WOFF_IN   0
#define WOFF_HID0 9216
#define WOFF_OUT  (9216 + 4 * 18432)   // 82944

__device__ __forceinline__ void mma_f16(float d[4], uint32_t a0, uint32_t a1,
                                        uint32_t a2, uint32_t a3,
                                        uint32_t b0, uint32_t b1) {
    asm volatile(
        "mma.sync.aligned.m16n8k16.row.col.f32.f16.f16.f32 "
        "{%0,%1,%2,%3}, {%4,%5,%6,%7}, {%8,%9}, {%0,%1,%2,%3};"
        : "+f"(d[0]), "+f"(d[1]), "+f"(d[2]), "+f"(d[3])
        : "r"(a0), "r"(a1), "r"(a2), "r"(a3), "r"(b0), "r"(b1));
}

__device__ __forceinline__ void cp_async16(uint32_t dst, const void* src, uint32_t srcsize) {
    asm volatile("cp.async.ca.shared.global [%0], [%1], 16, %2;"
                 :: "r"(dst), "l"(src), "r"(srcsize) : "memory");
}
__device__ __forceinline__ void cp_commit() {
    asm volatile("cp.async.commit_group;" ::: "memory");
}
__device__ __forceinline__ void cp_wait0() {
    asm volatile("cp.async.wait_group 0;" ::: "memory");
}
__device__ __forceinline__ uint32_t smem_u32(const void* p) {
    uint32_t a;
    asm("{ .reg .u64 t; cvta.to.shared.u64 t, %1; cvt.u32.u64 %0, t; }"
        : "=r"(a) : "l"(p));
    return a;
}
__device__ __forceinline__ uint32_t h2u(__half2 h) {
    uint32_t u; memcpy(&u, &h, 4); return u;
}

// ----------------------------------------------------------------------------
// weight prep: OIHW fp32 -> f16 B-fragment layout (one-time, 6 blocks).
// Channel permutation inside each 16-group matches X storage.
// chunk = (cg*9 + tap)*2 + (kin>>4)
// ----------------------------------------------------------------------------
__global__ __launch_bounds__(256)
void wprep_kernel(const float* __restrict__ w_in, const float* __restrict__ w1s,
                  const float* __restrict__ w2s, const float* __restrict__ w_out,
                  uint32_t* __restrict__ wfrag)
{
    const int layer = blockIdx.x;     // 0=in, 1..4=hidden, 5=out
    const int tid = threadIdx.x;

    const float* w;
    int cin, cout, woff, nwords, chunks, ntb;
    if (layer == 0)      { w = w_in;  cin = 25; cout = 64; woff = WOFF_IN;  nwords = 9216;  chunks = 18; ntb = 4; }
    else if (layer <= 4) {
        const int blk = (layer - 1) >> 1;
        w = ((layer - 1) & 1) ? (w2s + (size_t)blk * 64 * 64 * 9)
                              : (w1s + (size_t)blk * 64 * 64 * 9);
        cin = 64; cout = 64; woff = WOFF_HID0 + (layer - 1) * 18432; nwords = 18432; chunks = 36; ntb = 4;
    }
    else                 { w = w_out; cin = 64; cout = 9;  woff = WOFF_OUT; nwords = 4608; chunks = 36; ntb = 2; }

    for (int i = tid; i < nwords; i += 256) wfrag[woff + i] = 0u;
    __syncthreads();

    __half* wh = (__half*)(wfrag);
    const int wtot = cout * cin * 9;
    for (int i = tid; i < wtot; i += 256) {
        const int tap = i % 9;
        const int ci  = (i / 9) % cin;
        const int co  = i / (9 * cin);
        const int cg  = ci >> 5;
        const int kin = ci & 31;
        const int g2  = kin >> 4;
        const int k16 = kin & 15;
        const int chunk = (cg * 9 + tap) * 2 + g2;
        const int hi  = k16 >> 3;
        const int rem = k16 & 7;
        const int tt  = rem >> 1;
        const int hf  = rem & 1;
        const int lane = (co & 7) * 4 + tt;
        int word;
        if (ntb == 4) {
            const int nhalf = co >> 5;
            const int nt4   = (co >> 3) & 3;
            word = woff + nhalf * chunks * 256 + (chunk * 4 + nt4) * 64 + lane * 2 + hi;
        } else {
            const int nt = co >> 3;
            word = woff + (chunk * 2 + nt) * 64 + lane * 2 + hi;
        }
        wh[word * 2 + hf] = __float2half(w[i]);
    }
}

// ----------------------------------------------------------------------------
// prep: keyframe lerp -> fp16 permuted NHWC32 res_in
// ----------------------------------------------------------------------------
__global__ __launch_bounds__(256)
void prep_kernel(const float* __restrict__ latents, const int* __restrict__ idx,
                 __half* __restrict__ resin)
{
    const int n = blockIdx.x;
    const int b = n >> 7;
    const int t = n & 127;

    int v[9];
#pragma unroll
    for (int k = 0; k < 9; k++) v[k] = idx[b * 9 + k];
#pragma unroll
    for (int i = 1; i < 9; i++) {
        int key = v[i]; int j = i - 1;
        while (j >= 0 && v[j] > key) { v[j + 1] = v[j]; j--; }
        v[j + 1] = key;
    }
    int cnt = 0;
#pragma unroll
    for (int k = 0; k < 9; k++) cnt += (v[k] <= t);
    int seg = min(max(cnt - 1, 0), 7);
    const int t0 = v[seg], t1 = v[seg + 1];
    const float araw = (float)(t - t0) / (float)max(t1 - t0, 1);
    const float a = fminf(fmaxf(araw, 0.f), 1.f);

    const int tid = threadIdx.x;
    const float* L0 = latents + ((size_t)(b * 128 + t0)) * 8 * HW;
    const float* L1 = latents + ((size_t)(b * 128 + t1)) * 8 * HW;

#pragma unroll
    for (int j = 0; j < 4; j++) {
        const int p = tid + 256 * j;
        float buf[32];
#pragma unroll
        for (int c = 0; c < 8; c++) {
            const float z0 = L0[c * HW + p];
            const float z1 = L1[c * HW + p];
            buf[c]      = (1.f - a) * z0 + a * z1;
            buf[8 + c]  = z0;
            buf[16 + c] = z1;
        }
        buf[24] = a;
#pragma unroll
        for (int c = 25; c < 32; c++) buf[c] = 0.f;

        uint32_t wds[16];
#pragma unroll
        for (int g = 0; g < 2; g++)
#pragma unroll
            for (int jj = 0; jj < 8; jj++) {
                const int cl = ((jj >> 1) & 3) * 2 + (jj & 1) * 8;
                const int c  = g * 16 + cl;
                wds[g * 8 + jj] = h2u(__floats2half2_rn(buf[c], buf[c + 1]));
            }
        uint4* dst = (uint4*)(resin + ((size_t)n * HW + p) * 32);
#pragma unroll
        for (int q = 0; q < 4; q++)
            dst[q] = make_uint4(wds[q*4], wds[q*4+1], wds[q*4+2], wds[q*4+3]);
    }
}

// ----------------------------------------------------------------------------
// implicit-GEMM 3x3 SAME conv, mma.sync m16n8k16 fp16 (fp32 accum).
// Per-warp tile M64 x N = NTB*8. Grid (512,2) for 64-out layers.
// Slab-granularity double-buffered cp.async pipeline: stage s+1 issued after
// the stage-s sync, overlapping compute of stage s. 2 CTAs/SM.
// ----------------------------------------------------------------------------
template<int CG, int NTB, bool SILU, bool RESID>
__global__ __launch_bounds__(256, 2)
void conv_mma(const void* __restrict__ in_v, const uint32_t* __restrict__ wfrag,
              const float* __restrict__ bias, void* __restrict__ out_v,
              const void* __restrict__ resid_v)
{
    constexpr int CIN    = CG * 32;              // halves per pixel
    constexpr int CHUNKS = CG * 18;
    constexpr int BW     = CHUNKS * NTB * 64;    // B words
    constexpr int SLABS  = 2 * CG;               // 16-ch slab stages per tile
    constexpr int NSTAGE = 2 * SLABS;
    constexpr bool F16OUT = (NTB == 4);

    extern __shared__ uint32_t smem[];
    uint32_t* b_s = smem;            // BW words
    uint32_t* X_s = smem + BW;       // 2 buffers * 4896 words

    const int tid   = threadIdx.x;
    const int wid   = tid >> 5;
    const int lane  = tid & 31;
    const int n     = blockIdx.x;
    const int nhalf = blockIdx.y;
    const int tx    = lane >> 2;
    const int kq2   = (lane & 3) * 2;
    const int ch0   = F16OUT ? nhalf * 32 : 0;

    const uint32_t bs_u = smem_u32(b_s);
    const uint32_t xs_u = smem_u32(X_s);
    const char* in_b = (const char*)in_v + (size_t)n * HW * CIN * 2;

    // ---- stage B fragments (group 0, together with slab 0) ----
    const uint32_t* wsrc = wfrag + (size_t)nhalf * CHUNKS * NTB * 64;
    for (int i = tid; i < BW / 4; i += 256)
        cp_async16(bs_u + i * 16, wsrc + i * 4, 16);

    // ---- slab staging: 18x34 window, 16 channels (one k-slab) ----
    auto stage_slab = [&](int s) {
        const int tile = s / SLABS;
        const int k    = s - tile * SLABS;       // channel-slab index within pixel
        const uint32_t xoff = (uint32_t)((s & 1) * 4896 * 4);
#pragma unroll
        for (int q = 0; q < 5; q++) {
            const int i = tid + q * 256;
            if (q < 4 || i < 1224) {
                const int px   = i >> 1;
                const int part = i & 1;
                const int rr   = px / 34;
                const int gx   = px - rr * 34 - 1;
                const int gy   = tile * 16 - 1 + rr;
                const bool ok  = (gx >= 0) && (gx < 32) && (gy >= 0) && (gy < 32);
                const int pix  = ok ? (gy * 32 + gx) : 0;
                cp_async16(xs_u + xoff + (uint32_t)(px * 8 + part * 4) * 4,
                           in_b + (size_t)pix * CIN * 2 + part * 16 + k * 32,
                           ok ? 16u : 0u);
            }
        }
        cp_commit();
    };

    stage_slab(0);

    // bias -> registers
    float bv[NTB][2];
#pragma unroll
    for (int nt = 0; nt < NTB; nt++) {
        const int bi = ch0 + nt * 8 + kq2;
        bv[nt][0] = (F16OUT || bi     < 9) ? bias[bi]     : 0.f;
        bv[nt][1] = (F16OUT || bi + 1 < 9) ? bias[bi + 1] : 0.f;
    }

    float d[4][NTB][4];

#pragma unroll 1
    for (int s = 0; s < NSTAGE; s++) {
        const int tile = s / SLABS;
        const int k    = s - tile * SLABS;

        cp_wait0();
        __syncthreads();
        if (s + 1 < NSTAGE) stage_slab(s + 1);

        if (k == 0) {
#pragma unroll
            for (int f = 0; f < 4; f++)
#pragma unroll
                for (int nt = 0; nt < NTB; nt++)
#pragma unroll
                    for (int q = 0; q < 4; q++) d[f][nt][q] = 0.f;
        }

        const uint32_t* Xb = X_s + (s & 1) * 4896;
        const int cbase = (k >> 1) * 18 + (k & 1);    // chunk = cbase + tap*2

#pragma unroll
        for (int tap = 0; tap < 9; tap++) {
            const int dy = tap / 3, dx = tap - 3 * (tap / 3);
            const uint32_t* A = Xb + ((2 * wid + dy) * 34 + tx + dx) * 8 + kq2;
            const uint2 u0 = *(const uint2*)(A);          // row r,   px tx
            const uint2 u1 = *(const uint2*)(A + 64);     //          px tx+8
            const uint2 u2 = *(const uint2*)(A + 128);    //          px tx+16
            const uint2 u3 = *(const uint2*)(A + 192);    //          px tx+24
            const uint2 u4 = *(const uint2*)(A + 272);    // row r+1, px tx
            const uint2 u5 = *(const uint2*)(A + 336);
            const uint2 u6 = *(const uint2*)(A + 400);
            const uint2 u7 = *(const uint2*)(A + 464);
            const uint32_t* bp = b_s + (size_t)(cbase + tap * 2) * NTB * 64 + lane * 2;
#pragma unroll
            for (int nt = 0; nt < NTB; nt++) {
                const uint2 b = *(const uint2*)(bp + nt * 64);
                mma_f16(d[0][nt], u0.x, u1.x, u0.y, u1.y, b.x, b.y);
                mma_f16(d[1][nt], u2.x, u3.x, u2.y, u3.y, b.x, b.y);
                mma_f16(d[2][nt], u4.x, u5.x, u4.y, u5.y, b.x, b.y);
                mma_f16(d[3][nt], u6.x, u7.x, u6.y, u7.y, b.x, b.y);
            }
        }

        if (k == SLABS - 1) {
            // ---- epilogue for this tile ----
#pragma unroll
            for (int f = 0; f < 4; f++) {
                const int gy = tile * 16 + 2 * wid + (f >> 1);
                const int gx = ((f & 1) << 4) + tx;
                const size_t gp0 = (size_t)n * HW + gy * 32 + gx;
                const size_t gp1 = gp0 + 8;
#pragma unroll
                for (int nt = 0; nt < NTB; nt++) {
                    const int c = ch0 + nt * 8 + kq2;
                    float v00 = d[f][nt][0] + bv[nt][0];
                    float v01 = d[f][nt][1] + bv[nt][1];
                    float v10 = d[f][nt][2] + bv[nt][0];
                    float v11 = d[f][nt][3] + bv[nt][1];
                    if (SILU) {
                        v00 = __fdividef(v00, 1.f + __expf(-v00));
                        v01 = __fdividef(v01, 1.f + __expf(-v01));
                        v10 = __fdividef(v10, 1.f + __expf(-v10));
                        v11 = __fdividef(v11, 1.f + __expf(-v11));
                    }
                    if (F16OUT) {
                        const int g16 = c >> 4;
                        const int cl  = c & 15;
                        const int jl  = (((cl >> 3) & 1) << 1) | (((cl >> 1) & 3) << 2);
                        const size_t h0 = gp0 * 64 + g16 * 16 + jl;
                        const size_t h1 = gp1 * 64 + g16 * 16 + jl;
                        if (RESID) {
                            const __half2* rh = (const __half2*)resid_v;
                            const float2 r0 = __half22float2(rh[h0 >> 1]);
                            const float2 r1 = __half22float2(rh[h1 >> 1]);
                            v00 += r0.x; v01 += r0.y; v10 += r1.x; v11 += r1.y;
                        }
                        __half2* oh = (__half2*)out_v;
                        oh[h0 >> 1] = __floats2half2_rn(v00, v01);
                        oh[h1 >> 1] = __floats2half2_rn(v10, v11);
                    } else {
                        float* of = (float*)out_v;
                        *(float2*)(of + gp0 * 16 + c) = make_float2(v00, v01);
                        *(float2*)(of + gp1 * 16 + c) = make_float2(v10, v11);
                    }
                }
            }
        }
    }
}

// ----------------------------------------------------------------------------
// finalize: recompute fp32 z_base from latents; z_hat (NCHW) + conf
// ----------------------------------------------------------------------------
__global__ __launch_bounds__(256)
void finalize_kernel(const float* __restrict__ latents, const int* __restrict__ idx,
                     const float* __restrict__ co, float* __restrict__ outp)
{
    const int n = blockIdx.x;
    const int b = n >> 7;
    const int t = n & 127;

    int v[9];
#pragma unroll
    for (int k = 0; k < 9; k++) v[k] = idx[b * 9 + k];
#pragma unroll
    for (int i = 1; i < 9; i++) {
        int key = v[i]; int j = i - 1;
        while (j >= 0 && v[j] > key) { v[j + 1] = v[j]; j--; }
        v[j + 1] = key;
    }
    int cnt = 0;
#pragma unroll
    for (int k = 0; k < 9; k++) cnt += (v[k] <= t);
    int seg = min(max(cnt - 1, 0), 7);
    const int t0 = v[seg], t1 = v[seg + 1];
    const float araw = (float)(t - t0) / (float)max(t1 - t0, 1);
    const float a = fminf(fmaxf(araw, 0.f), 1.f);
    const float s = a * (1.f - a);
    const bool interior = (araw > 0.f) && (araw < 1.f);

    const int tid = threadIdx.x;
    const float* L0 = latents + ((size_t)(b * 128 + t0)) * 8 * HW;
    const float* L1 = latents + ((size_t)(b * 128 + t1)) * 8 * HW;

#pragma unroll
    for (int j = 0; j < 4; j++) {
        const int p = tid + 256 * j;
        const float* O = co + ((size_t)n * HW + p) * 16;
#pragma unroll
        for (int c = 0; c < 8; c++) {
            const float z0 = L0[c * HW + p];
            const float z1 = L1[c * HW + p];
            const float zb = (1.f - a) * z0 + a * z1;
            outp[((size_t)n * 8 + c) * HW + p] = zb + s * O[c];
        }
        const float unc = __fdividef(1.f, 1.f + __expf(-O[8]));
        outp[(size_t)NIMG * 8 * HW + (size_t)n * HW + p] =
            interior ? fminf(fmaxf(1.f - unc, 0.f), 1.f) : 1.f;
    }
}

// ----------------------------------------------------------------------------
// launch
// ----------------------------------------------------------------------------
extern "C" void kernel_launch(void* const* d_in, const int* in_sizes, int n_in,
                              void* d_out, int out_size)
{
    const float* latents = (const float*)d_in[0];
    const int*   idx     = (const int*)d_in[1];
    const float* w_in    = (const float*)d_in[2];
    const float* b_in    = (const float*)d_in[3];
    const float* w1s     = (const float*)d_in[4];
    const float* b1s     = (const float*)d_in[5];
    const float* w2s     = (const float*)d_in[6];
    const float* b2s     = (const float*)d_in[7];
    const float* w_out   = (const float*)d_in[8];
    const float* b_out   = (const float*)d_in[9];
    float* outp = (float*)d_out;

    __half *resin, *h, *tmp;
    float *coutb;
    uint32_t* wfrag;
    cudaGetSymbolAddress((void**)&resin, g_resin);
    cudaGetSymbolAddress((void**)&h,     g_h);
    cudaGetSymbolAddress((void**)&tmp,   g_tmp);
    cudaGetSymbolAddress((void**)&coutb, g_cout);
    cudaGetSymbolAddress((void**)&wfrag, g_wfrag);

    // dynamic smem: B + 2 X slab buffers (2*4896 words)
    constexpr int SM_IN  = ( 4608 + 9792) * 4;   // 57,600
    constexpr int SM_HID = ( 9216 + 9792) * 4;   // 76,032
    constexpr int SM_OUT = ( 4608 + 9792) * 4;   // 57,600

    cudaFuncSetAttribute(conv_mma<1, 4, true,  false>,
                         cudaFuncAttributeMaxDynamicSharedMemorySize, SM_IN);
    cudaFuncSetAttribute(conv_mma<2, 4, true,  false>,
                         cudaFuncAttributeMaxDynamicSharedMemorySize, SM_HID);
    cudaFuncSetAttribute(conv_mma<2, 4, false, true>,
                         cudaFuncAttributeMaxDynamicSharedMemorySize, SM_HID);
    cudaFuncSetAttribute(conv_mma<2, 2, false, false>,
                         cudaFuncAttributeMaxDynamicSharedMemorySize, SM_OUT);

    wprep_kernel<<<6, 256>>>(w_in, w1s, w2s, w_out, wfrag);
    prep_kernel<<<NIMG, 256>>>(latents, idx, resin);

    // conv_in: 25(->32) -> 64, SiLU   (N split across 2 CTAs)
    conv_mma<1, 4, true, false><<<dim3(NIMG, 2), 256, SM_IN>>>(
        resin, wfrag + WOFF_IN, b_in, h, nullptr);

    for (int blk = 0; blk < 2; blk++) {
        const float* b1 = b1s + blk * 64;
        const float* b2 = b2s + blk * 64;
        conv_mma<2, 4, true, false><<<dim3(NIMG, 2), 256, SM_HID>>>(
            h, wfrag + WOFF_HID0 + (2 * blk) * 18432, b1, tmp, nullptr);
        conv_mma<2, 4, false, true><<<dim3(NIMG, 2), 256, SM_HID>>>(
            tmp, wfrag + WOFF_HID0 + (2 * blk + 1) * 18432, b2, h, h);
    }

    // conv_out: 64 -> 9(->16), fp32 out
    conv_mma<2, 2, false, false><<<dim3(NIMG, 1), 256, SM_OUT>>>(
        h, wfrag + WOFF_OUT, b_out, coutb, nullptr);

    finalize_kernel<<<NIMG, 256>>>(latents, idx, coutb, outp);
}